// round 4
// baseline (speedup 1.0000x reference)
#include <cuda_runtime.h>
#include <cuda_fp16.h>
#include <stdint.h>

// Fixed problem shapes
#define NLAT_IN   181
#define NLON_IN   360
#define NLAT_OUT  361
#define NLON_OUT  720
#define KSIZE     3
#define CIN       16
#define COUT      16
#define NNZ_MAX   8192

#define X_CI_STRIDE (NLAT_IN * NLON_IN)          // 65160
#define PLANE       (KSIZE * NLAT_IN * NLON_IN)  // 195480
#define NBINS       (NLAT_OUT * 2)               // 722 (lat, parity)
#define SCAN_P      768
#define SE_MAX      512

#define NBLOCKS     592                          // 148 SMs * 4 blocks, one wave
#define EIN_UNITS   (2 * NLAT_IN)                // 362 einsum units
#define BIN_BLOCK   EIN_UNITS                    // block 362 does binning
#define GUNITS      (NLAT_OUT * 2)               // 722 gather units (ho, cg)

// Scratch (device globals — no dynamic allocation allowed)
__device__ uint4 g_xw8[2][PLANE];        // fp16-packed xw: plane cg = channels 8cg..8cg+7
__device__ int   g_starts[NBINS + 2];
__device__ int2  g_entries[NNZ_MAX];     // .x = base(18b)|shift<<18 ; .y = half2(v,v)
__device__ unsigned g_cnt  = 0;          // grid-barrier arrive counter
__device__ unsigned g_flag = 0;          // grid-barrier release flag (monotonic)
__device__ unsigned g_work = 0;          // gather work-stealing counter

__global__ __launch_bounds__(384, 4) void fused_kernel(
    const float* __restrict__ x, const float* __restrict__ weight,
    const int* __restrict__ ker_idx, const int* __restrict__ row_idx,
    const int* __restrict__ col_idx, const float* __restrict__ vals,
    const float* __restrict__ bias, float* __restrict__ out, int nnz)
{
    const int b  = blockIdx.x;
    const int t  = threadIdx.x;
    const int nt = blockDim.x;   // 384

    __shared__ int2 se[SE_MAX];
    __shared__ int  shdr[4];
    __shared__ int  s_u;
    __shared__ int  bufA[SCAN_P], bufB[SCAN_P];
    __shared__ int  scnt[NBINS], scur[NBINS];
    __shared__ float sw[8 * CIN * KSIZE];

    // ======================= PHASE A =======================
    if (b < EIN_UNITS) {
        // ----- einsum unit: 8 channels (cg), one input latitude (tin) -----
        const int tin = b >> 1;
        const int cg  = b & 1;

        if (t < 8 * CIN * KSIZE) sw[t] = weight[cg * 8 * CIN * KSIZE + t];
        __syncthreads();

        if (t < NLON_IN) {
            const float* xp = x + tin * NLON_IN + t;
            float acc[24];
            #pragma unroll
            for (int j = 0; j < 24; j++) acc[j] = 0.0f;

            // two passes of 8 input channels to bound register pressure
            #pragma unroll
            for (int half = 0; half < 2; half++) {
                float xv[8];
                #pragma unroll
                for (int c = 0; c < 8; c++)
                    xv[c] = __ldg(xp + (half * 8 + c) * X_CI_STRIDE);
                #pragma unroll
                for (int c = 0; c < 8; c++) {
                    int ci = half * 8 + c;
                    #pragma unroll
                    for (int cc = 0; cc < 8; cc++) {
                        #pragma unroll
                        for (int k = 0; k < KSIZE; k++) {
                            acc[cc * 3 + k] = fmaf(sw[(cc * CIN + ci) * KSIZE + k],
                                                   xv[c], acc[cc * 3 + k]);
                        }
                    }
                }
            }
            #pragma unroll
            for (int k = 0; k < KSIZE; k++) {
                __half2 h01 = __floats2half2_rn(acc[0 * 3 + k], acc[1 * 3 + k]);
                __half2 h23 = __floats2half2_rn(acc[2 * 3 + k], acc[3 * 3 + k]);
                __half2 h45 = __floats2half2_rn(acc[4 * 3 + k], acc[5 * 3 + k]);
                __half2 h67 = __floats2half2_rn(acc[6 * 3 + k], acc[7 * 3 + k]);
                uint4 u;
                u.x = *reinterpret_cast<unsigned int*>(&h01);
                u.y = *reinterpret_cast<unsigned int*>(&h23);
                u.z = *reinterpret_cast<unsigned int*>(&h45);
                u.w = *reinterpret_cast<unsigned int*>(&h67);
                g_xw8[cg][(k * NLAT_IN + tin) * NLON_IN + t] = u;
            }
        }
    } else if (b == BIN_BLOCK) {
        // ----- binning: count -> scan -> fill, all in smem -----
        for (int i = t; i < SCAN_P; i += nt) bufA[i] = 0;
        __syncthreads();
        for (int i = t; i < nnz; i += nt) {
            int col = col_idx[i];
            int hi  = col / NLON_OUT;
            atomicAdd(&bufA[hi * 2 + (col & 1)], 1);   // p parity == col parity
        }
        __syncthreads();
        for (int i = t; i < NBINS; i += nt) scnt[i] = bufA[i];
        __syncthreads();
        int* src = bufA; int* dst = bufB;
        for (int off = 1; off < SCAN_P; off <<= 1) {
            for (int i = t; i < SCAN_P; i += nt) {
                int v = src[i];
                if (i >= off) v += src[i - off];
                dst[i] = v;
            }
            __syncthreads();
            int* tmp = src; src = dst; dst = tmp;
        }
        for (int i = t; i < NBINS; i += nt) {
            g_starts[i + 1] = src[i];
            scur[i] = src[i] - scnt[i];
        }
        if (t == 0) g_starts[0] = 0;
        __syncthreads();
        for (int i = t; i < nnz; i += nt) {
            int col = col_idx[i];
            int hi  = col / NLON_OUT;
            int p   = col - hi * NLON_OUT;
            int key = hi * 2 + (p & 1);
            int pos = atomicAdd(&scur[key], 1);
            int base = (ker_idx[i] * NLAT_IN + row_idx[i]) * NLON_IN;  // < 2^18
            __half2 vh = __float2half2_rn(vals[i]);
            g_entries[pos] = make_int2(base | ((p >> 1) << 18),
                                       (int)*reinterpret_cast<unsigned int*>(&vh));
        }
    }

    // ======================= GRID BARRIER =======================
    __threadfence();
    __syncthreads();
    if (t == 0) {
        volatile unsigned* vflag = &g_flag;
        unsigned phase = *vflag;
        unsigned v = atomicAdd(&g_cnt, 1u);
        if (v == NBLOCKS - 1) {
            atomicExch(&g_cnt, 0u);
            atomicExch(&g_work, 0u);
            __threadfence();
            atomicAdd(&g_flag, 1u);
        } else {
            while (*vflag == phase) __nanosleep(64);
        }
        __threadfence();
    }
    // first __syncthreads of the work loop releases the block

    // ======================= PHASE B: gather =======================
    const __half2 hz = __float2half2_rn(0.0f);

    while (true) {
        __syncthreads();                 // also protects se reuse
        if (t == 0) s_u = (int)atomicAdd(&g_work, 1u);
        __syncthreads();
        const int u = s_u;
        if (u >= GUNITS) break;

        const int ho = u >> 1;
        const int cg = u & 1;

        if (t < 3) shdr[t] = g_starts[2 * ho + t];
        __syncthreads();
        const int s0 = shdr[0], s1 = shdr[1], s2 = shdr[2];
        const int n  = s2 - s0;

        const int2* ep;
        if (n <= SE_MAX) {
            for (int i = t; i < n; i += nt) se[i] = g_entries[s0 + i];
            __syncthreads();
            ep = se;
        } else {
            ep = &g_entries[s0];
        }

        if (t < NLON_IN) {
            const uint4* __restrict__ plane = g_xw8[cg];
            const int nE = s1 - s0;

            float aE[8], aO[8];
            #pragma unroll
            for (int c = 0; c < 8; c++) { aE[c] = 0.0f; aO[c] = 0.0f; }

            // even parity -> wo = 2t
            int i = 0;
            while (i < nE) {
                int lim = i + 4; if (lim > nE) lim = nE;
                __half2 h0 = hz, h1 = hz, h2 = hz, h3 = hz;
                for (; i < lim; i++) {
                    int2 e = ep[i];
                    unsigned ex = (unsigned)e.x;
                    int shift = ex >> 18;
                    int base  = ex & 0x3FFFF;
                    float vbits; *(int*)&vbits = e.y;
                    __half2 vh = *reinterpret_cast<__half2*>(&vbits);
                    int idx = t - shift; if (idx < 0) idx += NLON_IN;
                    uint4 uu = plane[base + idx];
                    h0 = __hfma2(vh, *reinterpret_cast<__half2*>(&uu.x), h0);
                    h1 = __hfma2(vh, *reinterpret_cast<__half2*>(&uu.y), h1);
                    h2 = __hfma2(vh, *reinterpret_cast<__half2*>(&uu.z), h2);
                    h3 = __hfma2(vh, *reinterpret_cast<__half2*>(&uu.w), h3);
                }
                float2 f;
                f = __half22float2(h0); aE[0] += f.x; aE[1] += f.y;
                f = __half22float2(h1); aE[2] += f.x; aE[3] += f.y;
                f = __half22float2(h2); aE[4] += f.x; aE[5] += f.y;
                f = __half22float2(h3); aE[6] += f.x; aE[7] += f.y;
            }
            // odd parity -> wo = 2t+1
            while (i < n) {
                int lim = i + 4; if (lim > n) lim = n;
                __half2 h0 = hz, h1 = hz, h2 = hz, h3 = hz;
                for (; i < lim; i++) {
                    int2 e = ep[i];
                    unsigned ex = (unsigned)e.x;
                    int shift = ex >> 18;
                    int base  = ex & 0x3FFFF;
                    float vbits; *(int*)&vbits = e.y;
                    __half2 vh = *reinterpret_cast<__half2*>(&vbits);
                    int idx = t - shift; if (idx < 0) idx += NLON_IN;
                    uint4 uu = plane[base + idx];
                    h0 = __hfma2(vh, *reinterpret_cast<__half2*>(&uu.x), h0);
                    h1 = __hfma2(vh, *reinterpret_cast<__half2*>(&uu.y), h1);
                    h2 = __hfma2(vh, *reinterpret_cast<__half2*>(&uu.z), h2);
                    h3 = __hfma2(vh, *reinterpret_cast<__half2*>(&uu.w), h3);
                }
                float2 f;
                f = __half22float2(h0); aO[0] += f.x; aO[1] += f.y;
                f = __half22float2(h1); aO[2] += f.x; aO[3] += f.y;
                f = __half22float2(h2); aO[4] += f.x; aO[5] += f.y;
                f = __half22float2(h3); aO[6] += f.x; aO[7] += f.y;
            }

            #pragma unroll
            for (int c = 0; c < 8; c++) {
                int co = cg * 8 + c;
                float bb = __ldg(&bias[co]);
                float2* row = (float2*)(out + (size_t)co * (NLAT_OUT * NLON_OUT)
                                        + ho * NLON_OUT);
                row[t] = make_float2(aE[c] + bb, aO[c] + bb);
            }
        }
    }
}

// ---------------------------------------------------------------------------
extern "C" void kernel_launch(void* const* d_in, const int* in_sizes, int n_in,
                              void* d_out, int out_size) {
    const float* x       = (const float*)d_in[0];
    const float* weight  = (const float*)d_in[1];
    const float* bias    = (const float*)d_in[2];
    const int*   ker_idx = (const int*)d_in[3];
    const int*   row_idx = (const int*)d_in[4];
    const int*   col_idx = (const int*)d_in[5];
    const float* vals    = (const float*)d_in[6];
    float* out = (float*)d_out;

    int nnz = in_sizes[3];
    if (nnz > NNZ_MAX) nnz = NNZ_MAX;

    fused_kernel<<<NBLOCKS, 384>>>(x, weight, ker_idx, row_idx, col_idx, vals,
                                   bias, out, nnz);
}

// round 5
// speedup vs baseline: 1.2604x; 1.2604x over previous
#include <cuda_runtime.h>
#include <cuda_fp16.h>
#include <stdint.h>

// Fixed problem shapes
#define NLAT_IN   181
#define NLON_IN   360
#define NLAT_OUT  361
#define NLON_OUT  720
#define KSIZE     3
#define CIN       16
#define COUT      16
#define NNZ_MAX   8192

#define X_CI_STRIDE (NLAT_IN * NLON_IN)          // 65160
#define PLANE       (KSIZE * NLAT_IN * NLON_IN)  // 195480
#define NBINS       (NLAT_OUT * 2)               // 722 (lat, parity)
#define SCAN_P      768
#define SE_MAX      512

#define EIN_UNITS   (2 * NLAT_IN)                // 362 einsum blocks
#define K1_BLOCKS   (EIN_UNITS + 1)              // +1 count/scan block

// Scratch (device globals — no dynamic allocation allowed)
__device__ uint4 g_xw8[2][PLANE];        // fp16-packed xw: plane cg = channels 8cg..8cg+7
__device__ int   g_starts[NBINS + 2];
__device__ int   g_cursor[NBINS];
__device__ int2  g_entries[NNZ_MAX];     // .x = base(18b)|shift<<18 ; .y = half2(v,v)

// ---------------------------------------------------------------------------
// K1: einsum (blocks 0..361) + count/scan (block 362).
__global__ __launch_bounds__(384) void einsum_binscan_kernel(
    const float* __restrict__ x, const float* __restrict__ weight,
    const int* __restrict__ col_idx, int nnz)
{
    const int b  = blockIdx.x;
    const int t  = threadIdx.x;
    const int nt = blockDim.x;   // 384

    if (b == EIN_UNITS) {
        // ---- count + scan only (fill is a separate parallel kernel) ----
        __shared__ int bufA[SCAN_P], bufB[SCAN_P];
        __shared__ int scnt[NBINS];

        for (int i = t; i < SCAN_P; i += nt) bufA[i] = 0;
        __syncthreads();
        for (int i = t; i < nnz; i += nt) {
            int col = col_idx[i];
            int hi  = col / NLON_OUT;
            atomicAdd(&bufA[hi * 2 + (col & 1)], 1);   // p parity == col parity
        }
        __syncthreads();
        for (int i = t; i < NBINS; i += nt) scnt[i] = bufA[i];
        __syncthreads();
        int* src = bufA; int* dst = bufB;
        for (int off = 1; off < SCAN_P; off <<= 1) {
            for (int i = t; i < SCAN_P; i += nt) {
                int v = src[i];
                if (i >= off) v += src[i - off];
                dst[i] = v;
            }
            __syncthreads();
            int* tmp = src; src = dst; dst = tmp;
        }
        for (int i = t; i < NBINS; i += nt) {
            g_starts[i + 1] = src[i];
            g_cursor[i]     = src[i] - scnt[i];   // exclusive prefix = bin start
        }
        if (t == 0) g_starts[0] = 0;
        return;
    }

    // ---- einsum block: 8 channels (cg), one input latitude (tin) ----
    const int tin = b >> 1;
    const int cg  = b & 1;

    __shared__ float sw[8 * CIN * KSIZE];
    if (t < 8 * CIN * KSIZE) sw[t] = weight[cg * 8 * CIN * KSIZE + t];
    __syncthreads();
    if (t >= NLON_IN) return;

    const float* xp = x + tin * NLON_IN + t;
    float acc[24];
    #pragma unroll
    for (int j = 0; j < 24; j++) acc[j] = 0.0f;

    #pragma unroll
    for (int half = 0; half < 2; half++) {
        float xv[8];
        #pragma unroll
        for (int c = 0; c < 8; c++)
            xv[c] = __ldg(xp + (half * 8 + c) * X_CI_STRIDE);
        #pragma unroll
        for (int c = 0; c < 8; c++) {
            int ci = half * 8 + c;
            #pragma unroll
            for (int cc = 0; cc < 8; cc++) {
                #pragma unroll
                for (int k = 0; k < KSIZE; k++) {
                    acc[cc * 3 + k] = fmaf(sw[(cc * CIN + ci) * KSIZE + k],
                                           xv[c], acc[cc * 3 + k]);
                }
            }
        }
    }
    #pragma unroll
    for (int k = 0; k < KSIZE; k++) {
        __half2 h01 = __floats2half2_rn(acc[0 * 3 + k], acc[1 * 3 + k]);
        __half2 h23 = __floats2half2_rn(acc[2 * 3 + k], acc[3 * 3 + k]);
        __half2 h45 = __floats2half2_rn(acc[4 * 3 + k], acc[5 * 3 + k]);
        __half2 h67 = __floats2half2_rn(acc[6 * 3 + k], acc[7 * 3 + k]);
        uint4 u;
        u.x = *reinterpret_cast<unsigned int*>(&h01);
        u.y = *reinterpret_cast<unsigned int*>(&h23);
        u.z = *reinterpret_cast<unsigned int*>(&h45);
        u.w = *reinterpret_cast<unsigned int*>(&h67);
        g_xw8[cg][(k * NLAT_IN + tin) * NLON_IN + t] = u;
    }
}

// ---------------------------------------------------------------------------
// K2: parallel fill via global per-bin cursors.
__global__ void fill_kernel(const int* __restrict__ ker_idx,
                            const int* __restrict__ row_idx,
                            const int* __restrict__ col_idx,
                            const float* __restrict__ vals, int nnz)
{
    int i = blockIdx.x * blockDim.x + threadIdx.x;
    if (i >= nnz) return;
    int col = col_idx[i];
    int hi  = col / NLON_OUT;
    int p   = col - hi * NLON_OUT;
    int key = hi * 2 + (p & 1);
    int pos = atomicAdd(&g_cursor[key], 1);
    int base = (ker_idx[i] * NLAT_IN + row_idx[i]) * NLON_IN;  // < 2^18
    __half2 vh = __float2half2_rn(vals[i]);
    g_entries[pos] = make_int2(base | ((p >> 1) << 18),
                               (int)*reinterpret_cast<unsigned int*>(&vh));
}

// ---------------------------------------------------------------------------
// K3: gather — grid (NLAT_OUT, 2). Block (ho, cg): thread t owns output lons
// (2t, 2t+1) for channels {8cg..8cg+7}; one uint4 load + 4 HFMA2 per entry.
__global__ __launch_bounds__(384) void gather_kernel(
    float* __restrict__ out, const float* __restrict__ bias)
{
    const int ho = blockIdx.x;
    const int cg = blockIdx.y;
    const int t  = threadIdx.x;
    const int nt = blockDim.x;

    __shared__ int2 se[SE_MAX];
    __shared__ int shdr[3];
    if (t < 3) shdr[t] = g_starts[2 * ho + t];
    __syncthreads();
    const int s0 = shdr[0], s1 = shdr[1], s2 = shdr[2];
    const int n = s2 - s0;

    const int2* ep;
    if (n <= SE_MAX) {
        for (int i = t; i < n; i += nt) se[i] = g_entries[s0 + i];
        __syncthreads();
        ep = se;
    } else {
        ep = &g_entries[s0];
    }

    if (t >= NLON_IN) return;

    const uint4* __restrict__ plane = g_xw8[cg];
    const __half2 hz = __float2half2_rn(0.0f);

    float aE[8], aO[8];
    #pragma unroll
    for (int c = 0; c < 8; c++) { aE[c] = 0.0f; aO[c] = 0.0f; }

    const int nE = s1 - s0;
    // even parity -> wo = 2t
    int i = 0;
    while (i < nE) {
        int lim = i + 4; if (lim > nE) lim = nE;
        __half2 h0 = hz, h1 = hz, h2 = hz, h3 = hz;
        #pragma unroll 2
        for (; i < lim; i++) {
            int2 e = ep[i];
            unsigned ex = (unsigned)e.x;
            int shift = ex >> 18;
            int base  = ex & 0x3FFFF;
            float vbits; *(int*)&vbits = e.y;
            __half2 vh = *reinterpret_cast<__half2*>(&vbits);
            int idx = t - shift; if (idx < 0) idx += NLON_IN;
            uint4 uu = plane[base + idx];
            h0 = __hfma2(vh, *reinterpret_cast<__half2*>(&uu.x), h0);
            h1 = __hfma2(vh, *reinterpret_cast<__half2*>(&uu.y), h1);
            h2 = __hfma2(vh, *reinterpret_cast<__half2*>(&uu.z), h2);
            h3 = __hfma2(vh, *reinterpret_cast<__half2*>(&uu.w), h3);
        }
        float2 f;
        f = __half22float2(h0); aE[0] += f.x; aE[1] += f.y;
        f = __half22float2(h1); aE[2] += f.x; aE[3] += f.y;
        f = __half22float2(h2); aE[4] += f.x; aE[5] += f.y;
        f = __half22float2(h3); aE[6] += f.x; aE[7] += f.y;
    }
    // odd parity -> wo = 2t+1
    while (i < n) {
        int lim = i + 4; if (lim > n) lim = n;
        __half2 h0 = hz, h1 = hz, h2 = hz, h3 = hz;
        #pragma unroll 2
        for (; i < lim; i++) {
            int2 e = ep[i];
            unsigned ex = (unsigned)e.x;
            int shift = ex >> 18;
            int base  = ex & 0x3FFFF;
            float vbits; *(int*)&vbits = e.y;
            __half2 vh = *reinterpret_cast<__half2*>(&vbits);
            int idx = t - shift; if (idx < 0) idx += NLON_IN;
            uint4 uu = plane[base + idx];
            h0 = __hfma2(vh, *reinterpret_cast<__half2*>(&uu.x), h0);
            h1 = __hfma2(vh, *reinterpret_cast<__half2*>(&uu.y), h1);
            h2 = __hfma2(vh, *reinterpret_cast<__half2*>(&uu.z), h2);
            h3 = __hfma2(vh, *reinterpret_cast<__half2*>(&uu.w), h3);
        }
        float2 f;
        f = __half22float2(h0); aO[0] += f.x; aO[1] += f.y;
        f = __half22float2(h1); aO[2] += f.x; aO[3] += f.y;
        f = __half22float2(h2); aO[4] += f.x; aO[5] += f.y;
        f = __half22float2(h3); aO[6] += f.x; aO[7] += f.y;
    }

    #pragma unroll
    for (int c = 0; c < 8; c++) {
        int co = cg * 8 + c;
        float bb = __ldg(&bias[co]);
        float2* row = (float2*)(out + (size_t)co * (NLAT_OUT * NLON_OUT) + ho * NLON_OUT);
        row[t] = make_float2(aE[c] + bb, aO[c] + bb);
    }
}

// ---------------------------------------------------------------------------
extern "C" void kernel_launch(void* const* d_in, const int* in_sizes, int n_in,
                              void* d_out, int out_size) {
    const float* x       = (const float*)d_in[0];
    const float* weight  = (const float*)d_in[1];
    const float* bias    = (const float*)d_in[2];
    const int*   ker_idx = (const int*)d_in[3];
    const int*   row_idx = (const int*)d_in[4];
    const int*   col_idx = (const int*)d_in[5];
    const float* vals    = (const float*)d_in[6];
    float* out = (float*)d_out;

    int nnz = in_sizes[3];
    if (nnz > NNZ_MAX) nnz = NNZ_MAX;

    einsum_binscan_kernel<<<K1_BLOCKS, 384>>>(x, weight, col_idx, nnz);
    fill_kernel<<<(nnz + 255) / 256, 256>>>(ker_idx, row_idx, col_idx, vals, nnz);

    dim3 ggrid(NLAT_OUT, 2);
    gather_kernel<<<ggrid, 384>>>(out, bias);
}

// round 7
// speedup vs baseline: 1.2695x; 1.0072x over previous
#include <cuda_runtime.h>
#include <cuda_fp16.h>
#include <stdint.h>

// Fixed problem shapes
#define NLAT_IN   181
#define NLON_IN   360
#define NLAT_OUT  361
#define NLON_OUT  720
#define KSIZE     3
#define CIN       16
#define COUT      16
#define NNZ_MAX   8192

#define X_CI_STRIDE (NLAT_IN * NLON_IN)          // 65160
#define PLANE       (KSIZE * NLAT_IN * NLON_IN)  // 195480
#define NBINS       (NLAT_OUT * 2)               // 722 (lat, parity)
#define SCAN_P      768
#define SE_MAX      512

#define EIN_UNITS   (NLAT_IN * 6)                // 1086 einsum blocks (tin, cg, k)
#define K1_BLOCKS   (EIN_UNITS + 1)              // +1 count/scan block
#define XTILE       (CIN * NLON_IN)              // 5760 floats

// Scratch (device globals — no dynamic allocation allowed)
__device__ uint4 g_xw8[2][PLANE];        // fp16-packed xw: plane cg = channels 8cg..8cg+7
__device__ int   g_starts[NBINS + 2];
__device__ int   g_cursor[NBINS];
__device__ int2  g_entries[NNZ_MAX];     // .x = base(18b)|shift<<18 ; .y = half2(v,v)

// ---------------------------------------------------------------------------
// K1: einsum (blocks 0..1085: one per (tin, cg, k)) + count/scan (block 1086).
__global__ __launch_bounds__(384) void einsum_binscan_kernel(
    const float* __restrict__ x, const float* __restrict__ weight,
    const int* __restrict__ col_idx, int nnz)
{
    const int b  = blockIdx.x;
    const int t  = threadIdx.x;
    const int nt = blockDim.x;   // 384

    __shared__ float smf[XTILE + 128];   // 23.5 KB: x tile + packed weights

    if (b == EIN_UNITS) {
        // ---- count + scan only (fill is a separate parallel kernel) ----
        int* bufA = (int*)smf;
        int* bufB = bufA + SCAN_P;
        int* scnt = bufB + SCAN_P;       // NBINS ints; total fits in smf

        for (int i = t; i < SCAN_P; i += nt) bufA[i] = 0;
        __syncthreads();
        for (int i = t; i < nnz; i += nt) {
            int col = col_idx[i];
            int hi  = col / NLON_OUT;
            atomicAdd(&bufA[hi * 2 + (col & 1)], 1);   // p parity == col parity
        }
        __syncthreads();
        for (int i = t; i < NBINS; i += nt) scnt[i] = bufA[i];
        __syncthreads();
        int* src = bufA; int* dst = bufB;
        for (int off = 1; off < SCAN_P; off <<= 1) {
            for (int i = t; i < SCAN_P; i += nt) {
                int v = src[i];
                if (i >= off) v += src[i - off];
                dst[i] = v;
            }
            __syncthreads();
            int* tmp = src; src = dst; dst = tmp;
        }
        for (int i = t; i < NBINS; i += nt) {
            g_starts[i + 1] = src[i];
            g_cursor[i]     = src[i] - scnt[i];   // exclusive prefix = bin start
        }
        if (t == 0) g_starts[0] = 0;
        return;
    }

    // ---- einsum block: (tin, cg, k); 8 accumulators per thread ----
    const int tin = b / 6;
    const int r   = b - tin * 6;
    const int cg  = r >> 1 ? (r >= 3) : 0;  // placeholder, replaced below
    (void)cg;
    const int cgv = r / 3;                  // 0 or 1
    const int k   = r - cgv * 3;            // 0..2

    float* sx  = smf;                       // [16][360]
    float* sw4 = smf + XTILE;               // 128 floats = 2 groups x 16ci x float4(cc)

    // pack weights: sw4[((cc>>2)*16 + ci)*4 + (cc&3)] = weight[((cgv*8+cc)*CIN+ci)*KSIZE + k]
    if (t < 128) {
        int cc = t >> 4;          // 0..7
        int ci = t & 15;          // 0..15
        sw4[((cc >> 2) * 16 + ci) * 4 + (cc & 3)] =
            weight[((cgv * 8 + cc) * CIN + ci) * KSIZE + k];
    }
    // stage x tile coalesced: sx[ci*360+po] = x[ci][tin][po]
    #pragma unroll
    for (int j = 0; j < XTILE / 384; j++) {      // 15 iters
        int i  = t + j * 384;
        int ci = i / NLON_IN;
        int po = i - ci * NLON_IN;
        sx[i] = x[ci * X_CI_STRIDE + tin * NLON_IN + po];
    }
    __syncthreads();
    if (t >= NLON_IN) return;

    float a0 = 0.f, a1 = 0.f, a2 = 0.f, a3 = 0.f;
    float a4 = 0.f, a5 = 0.f, a6 = 0.f, a7 = 0.f;
    const float4* w4 = (const float4*)sw4;

    #pragma unroll
    for (int ci = 0; ci < CIN; ci++) {
        float xv = sx[ci * NLON_IN + t];
        float4 wlo = w4[ci];          // cc 0..3
        float4 whi = w4[16 + ci];     // cc 4..7
        a0 = fmaf(wlo.x, xv, a0);  a1 = fmaf(wlo.y, xv, a1);
        a2 = fmaf(wlo.z, xv, a2);  a3 = fmaf(wlo.w, xv, a3);
        a4 = fmaf(whi.x, xv, a4);  a5 = fmaf(whi.y, xv, a5);
        a6 = fmaf(whi.z, xv, a6);  a7 = fmaf(whi.w, xv, a7);
    }

    __half2 h01 = __floats2half2_rn(a0, a1);
    __half2 h23 = __floats2half2_rn(a2, a3);
    __half2 h45 = __floats2half2_rn(a4, a5);
    __half2 h67 = __floats2half2_rn(a6, a7);
    uint4 u;
    u.x = *reinterpret_cast<unsigned int*>(&h01);
    u.y = *reinterpret_cast<unsigned int*>(&h23);
    u.z = *reinterpret_cast<unsigned int*>(&h45);
    u.w = *reinterpret_cast<unsigned int*>(&h67);
    g_xw8[cgv][(k * NLAT_IN + tin) * NLON_IN + t] = u;
}

// ---------------------------------------------------------------------------
// K2: parallel fill via global per-bin cursors.
__global__ void fill_kernel(const int* __restrict__ ker_idx,
                            const int* __restrict__ row_idx,
                            const int* __restrict__ col_idx,
                            const float* __restrict__ vals, int nnz)
{
    int i = blockIdx.x * blockDim.x + threadIdx.x;
    if (i >= nnz) return;
    int col = col_idx[i];
    int hi  = col / NLON_OUT;
    int p   = col - hi * NLON_OUT;
    int key = hi * 2 + (p & 1);
    int pos = atomicAdd(&g_cursor[key], 1);
    int base = (ker_idx[i] * NLAT_IN + row_idx[i]) * NLON_IN;  // < 2^18
    __half2 vh = __float2half2_rn(vals[i]);
    g_entries[pos] = make_int2(base | ((p >> 1) << 18),
                               (int)*reinterpret_cast<unsigned int*>(&vh));
}

// ---------------------------------------------------------------------------
// Per-entry decode helper
__device__ __forceinline__ int dec_addr(int2 e, int t, __half2& vh) {
    unsigned ex = (unsigned)e.x;
    int shift = ex >> 18;
    int base  = ex & 0x3FFFF;
    float vbits; *(int*)&vbits = e.y;
    vh = *reinterpret_cast<__half2*>(&vbits);
    int idx = t - shift; if (idx < 0) idx += NLON_IN;
    return base + idx;
}

// K3: gather — grid (NLAT_OUT, 2). Block (ho, cg): thread t owns output lons
// (2t, 2t+1) for channels {8cg..8cg+7}. MLP-4 pipelined inner loop.
__global__ __launch_bounds__(384) void gather_kernel(
    float* __restrict__ out, const float* __restrict__ bias)
{
    const int ho = blockIdx.x;
    const int cg = blockIdx.y;
    const int t  = threadIdx.x;
    const int nt = blockDim.x;

    __shared__ int2 se[SE_MAX];
    __shared__ int shdr[3];
    if (t < 3) shdr[t] = g_starts[2 * ho + t];
    __syncthreads();
    const int s0 = shdr[0], s1 = shdr[1], s2 = shdr[2];
    const int n = s2 - s0;

    const int2* ep;
    if (n <= SE_MAX) {
        for (int i = t; i < n; i += nt) se[i] = g_entries[s0 + i];
        __syncthreads();
        ep = se;
    } else {
        ep = &g_entries[s0];
    }

    if (t >= NLON_IN) return;

    const uint4* __restrict__ plane = g_xw8[cg];
    const __half2 hz = __float2half2_rn(0.0f);

    float aE[8], aO[8];
    #pragma unroll
    for (int c = 0; c < 8; c++) { aE[c] = 0.0f; aO[c] = 0.0f; }

    const int nE = s1 - s0;

    #pragma unroll 1
    for (int par = 0; par < 2; par++) {
        int i   = par ? nE : 0;
        int end = par ? n  : nE;
        float* acc = par ? aO : aE;

        // MLP-4 batches
        while (end - i >= 4) {
            __half2 v0, v1, v2, v3;
            int a0 = dec_addr(ep[i + 0], t, v0);
            int a1 = dec_addr(ep[i + 1], t, v1);
            int a2 = dec_addr(ep[i + 2], t, v2);
            int a3 = dec_addr(ep[i + 3], t, v3);
            uint4 u0 = plane[a0];
            uint4 u1 = plane[a1];
            uint4 u2 = plane[a2];
            uint4 u3 = plane[a3];
            __half2 h0 = hz, h1 = hz, h2 = hz, h3 = hz;
            h0 = __hfma2(v0, *reinterpret_cast<__half2*>(&u0.x), h0);
            h1 = __hfma2(v0, *reinterpret_cast<__half2*>(&u0.y), h1);
            h2 = __hfma2(v0, *reinterpret_cast<__half2*>(&u0.z), h2);
            h3 = __hfma2(v0, *reinterpret_cast<__half2*>(&u0.w), h3);
            h0 = __hfma2(v1, *reinterpret_cast<__half2*>(&u1.x), h0);
            h1 = __hfma2(v1, *reinterpret_cast<__half2*>(&u1.y), h1);
            h2 = __hfma2(v1, *reinterpret_cast<__half2*>(&u1.z), h2);
            h3 = __hfma2(v1, *reinterpret_cast<__half2*>(&u1.w), h3);
            h0 = __hfma2(v2, *reinterpret_cast<__half2*>(&u2.x), h0);
            h1 = __hfma2(v2, *reinterpret_cast<__half2*>(&u2.y), h1);
            h2 = __hfma2(v2, *reinterpret_cast<__half2*>(&u2.z), h2);
            h3 = __hfma2(v2, *reinterpret_cast<__half2*>(&u2.w), h3);
            h0 = __hfma2(v3, *reinterpret_cast<__half2*>(&u3.x), h0);
            h1 = __hfma2(v3, *reinterpret_cast<__half2*>(&u3.y), h1);
            h2 = __hfma2(v3, *reinterpret_cast<__half2*>(&u3.z), h2);
            h3 = __hfma2(v3, *reinterpret_cast<__half2*>(&u3.w), h3);
            float2 f;
            f = __half22float2(h0); acc[0] += f.x; acc[1] += f.y;
            f = __half22float2(h1); acc[2] += f.x; acc[3] += f.y;
            f = __half22float2(h2); acc[4] += f.x; acc[5] += f.y;
            f = __half22float2(h3); acc[6] += f.x; acc[7] += f.y;
            i += 4;
        }
        // tail
        while (i < end) {
            __half2 v0;
            int a0 = dec_addr(ep[i], t, v0);
            uint4 u0 = plane[a0];
            float2 f, vf = __half22float2(v0);
            float2 g;
            g = __half22float2(*reinterpret_cast<__half2*>(&u0.x));
            acc[0] = fmaf(vf.x, g.x, acc[0]); acc[1] = fmaf(vf.x, g.y, acc[1]);
            g = __half22float2(*reinterpret_cast<__half2*>(&u0.y));
            acc[2] = fmaf(vf.x, g.x, acc[2]); acc[3] = fmaf(vf.x, g.y, acc[3]);
            g = __half22float2(*reinterpret_cast<__half2*>(&u0.z));
            acc[4] = fmaf(vf.x, g.x, acc[4]); acc[5] = fmaf(vf.x, g.y, acc[5]);
            g = __half22float2(*reinterpret_cast<__half2*>(&u0.w));
            acc[6] = fmaf(vf.x, g.x, acc[6]); acc[7] = fmaf(vf.x, g.y, acc[7]);
            (void)f;
            i++;
        }
    }

    #pragma unroll
    for (int c = 0; c < 8; c++) {
        int co = cg * 8 + c;
        float bb = __ldg(&bias[co]);
        float2* row = (float2*)(out + (size_t)co * (NLAT_OUT * NLON_OUT) + ho * NLON_OUT);
        row[t] = make_float2(aE[c] + bb, aO[c] + bb);
    }
}

// ---------------------------------------------------------------------------
extern "C" void kernel_launch(void* const* d_in, const int* in_sizes, int n_in,
                              void* d_out, int out_size) {
    const float* x       = (const float*)d_in[0];
    const float* weight  = (const float*)d_in[1];
    const float* bias    = (const float*)d_in[2];
    const int*   ker_idx = (const int*)d_in[3];
    const int*   row_idx = (const int*)d_in[4];
    const int*   col_idx = (const int*)d_in[5];
    const float* vals    = (const float*)d_in[6];
    float* out = (float*)d_out;

    int nnz = in_sizes[3];
    if (nnz > NNZ_MAX) nnz = NNZ_MAX;

    einsum_binscan_kernel<<<K1_BLOCKS, 384>>>(x, weight, col_idx, nnz);
    fill_kernel<<<(nnz + 255) / 256, 256>>>(ker_idx, row_idx, col_idx, vals, nnz);

    dim3 ggrid(NLAT_OUT, 2);
    gather_kernel<<<ggrid, 384>>>(out, bias);
}